// round 1
// baseline (speedup 1.0000x reference)
#include <cuda_runtime.h>
#include <cstdint>

// FOFE encoding:
//   out[b,s,v] = sum_k alpha^(W-1-k) * [sents[b,s,k] == v],  V=512, W=20
//   plus lengths passthrough (cast to float) if the harness flattened the tuple.

#define FOFE_V 512
#define FOFE_W 20
#define WARPS_PER_BLOCK 8

__global__ void fofe_kernel(const int* __restrict__ sents,
                            const float* __restrict__ forgetting,
                            float* __restrict__ out,
                            int n_rows) {
    __shared__ float sh[WARPS_PER_BLOCK][FOFE_V];

    const int warp = threadIdx.x >> 5;
    const int lane = threadIdx.x & 31;
    const int row  = blockIdx.x * WARPS_PER_BLOCK + warp;
    if (row >= n_rows) return;

    float* s = sh[warp];

    // zero the 512-float row buffer (16 floats/lane)
    #pragma unroll
    for (int i = lane; i < FOFE_V; i += 32) s[i] = 0.0f;
    __syncwarp();

    // lanes 0..19: scatter-add decay weight into shared
    if (lane < FOFE_W) {
        const float alpha = forgetting[0];
        int c = sents[(size_t)row * FOFE_W + lane];
        // w = alpha^(W-1-lane), exact iterative multiply (<=19 FMULs)
        float w = 1.0f;
        int e = FOFE_W - 1 - lane;
        #pragma unroll
        for (int j = 0; j < FOFE_W - 1; j++) {
            if (j < e) w *= alpha;
        }
        atomicAdd(&s[c], w);
    }
    __syncwarp();

    // stream out 512 floats as float4 (128 float4, 4 per lane), coalesced
    float4* o  = reinterpret_cast<float4*>(out + (size_t)row * FOFE_V);
    const float4* sv = reinterpret_cast<const float4*>(s);
    #pragma unroll
    for (int i = lane; i < FOFE_V / 4; i += 32) o[i] = sv[i];
}

__global__ void lengths_tail_kernel(const int* __restrict__ lengths,
                                    float* __restrict__ out_tail,
                                    int n) {
    int i = blockIdx.x * blockDim.x + threadIdx.x;
    if (i < n) out_tail[i] = (float)lengths[i];
}

extern "C" void kernel_launch(void* const* d_in, const int* in_sizes, int n_in,
                              void* d_out, int out_size) {
    const int*   sents      = (const int*)d_in[0];
    const int*   lengths    = (const int*)d_in[1];
    const float* forgetting = (const float*)d_in[2];
    float*       out        = (float*)d_out;

    const int n_rows = in_sizes[0] / FOFE_W;      // B*S
    const int B      = in_sizes[1];

    const int threads = WARPS_PER_BLOCK * 32;
    const int blocks  = (n_rows + WARPS_PER_BLOCK - 1) / WARPS_PER_BLOCK;
    fofe_kernel<<<blocks, threads>>>(sents, forgetting, out, n_rows);

    // If the harness flattened the (out, lengths) tuple, write lengths tail.
    const long long main_elems = (long long)n_rows * FOFE_V;
    if ((long long)out_size > main_elems) {
        int tail = (int)((long long)out_size - main_elems);
        int t = tail < B ? tail : B;
        lengths_tail_kernel<<<(t + 127) / 128, 128>>>(lengths, out + main_elems, t);
    }
}

// round 2
// speedup vs baseline: 1.2194x; 1.2194x over previous
#include <cuda_runtime.h>
#include <cstdint>

// FOFE encoding:
//   out[b,s,v] = sum_k alpha^(W-1-k) * [sents[b,s,k] == v],  V=512, W=20
//   fused lengths passthrough written by block 0.

#define FOFE_V 512
#define FOFE_W 20
#define WARPS_PER_BLOCK 8

__global__ void fofe_fused_kernel(const int* __restrict__ sents,
                                  const int* __restrict__ lengths,
                                  const float* __restrict__ forgetting,
                                  float* __restrict__ out,
                                  int n_rows, int tail_n) {
    __shared__ float sh[WARPS_PER_BLOCK][FOFE_V];

    const int warp = threadIdx.x >> 5;
    const int lane = threadIdx.x & 31;
    const int row  = blockIdx.x * WARPS_PER_BLOCK + warp;

    // fused lengths tail: block 0's first tail_n threads (tail_n <= 256)
    if (blockIdx.x == 0 && (int)threadIdx.x < tail_n) {
        out[(size_t)n_rows * FOFE_V + threadIdx.x] = (float)lengths[threadIdx.x];
    }

    if (row >= n_rows) return;

    float* s = sh[warp];

    // zero the 512-float row buffer (16 floats/lane)
    #pragma unroll
    for (int i = lane; i < FOFE_V; i += 32) s[i] = 0.0f;
    __syncwarp();

    // lanes 0..19: scatter-add decay weight into shared
    if (lane < FOFE_W) {
        const float alpha = forgetting[0];
        const int c = sents[(size_t)row * FOFE_W + lane];
        // w = alpha^(W-1-lane), iterative multiply (<=19 FMULs)
        float w = 1.0f;
        const int e = FOFE_W - 1 - lane;
        #pragma unroll
        for (int j = 0; j < FOFE_W - 1; j++) {
            if (j < e) w *= alpha;
        }
        atomicAdd(&s[c], w);
    }
    __syncwarp();

    // stream out 512 floats as float4 (128 float4, 4 per lane), coalesced,
    // streaming (evict-first) since the output is never re-read.
    float* orow = out + (size_t)row * FOFE_V;
    const float4* sv = reinterpret_cast<const float4*>(s);
    #pragma unroll
    for (int i = 0; i < 4; i++) {
        const int idx = lane + i * 32;
        __stcs(reinterpret_cast<float4*>(orow) + idx, sv[idx]);
    }
}

extern "C" void kernel_launch(void* const* d_in, const int* in_sizes, int n_in,
                              void* d_out, int out_size) {
    const int*   sents      = (const int*)d_in[0];
    const int*   lengths    = (const int*)d_in[1];
    const float* forgetting = (const float*)d_in[2];
    float*       out        = (float*)d_out;

    const int n_rows = in_sizes[0] / FOFE_W;      // B*S
    const int B      = in_sizes[1];

    // tail elements (lengths passthrough) if the harness flattened the tuple
    const long long main_elems = (long long)n_rows * FOFE_V;
    int tail_n = 0;
    if ((long long)out_size > main_elems) {
        long long t = (long long)out_size - main_elems;
        tail_n = (int)(t < B ? t : B);
        if (tail_n > 256) tail_n = 256;  // block 0 handles up to 256
    }

    const int threads = WARPS_PER_BLOCK * 32;
    const int blocks  = (n_rows + WARPS_PER_BLOCK - 1) / WARPS_PER_BLOCK;
    fofe_fused_kernel<<<blocks, threads>>>(sents, lengths, forgetting, out,
                                           n_rows, tail_n);
}